// round 2
// baseline (speedup 1.0000x reference)
#include <cuda_runtime.h>

#define DIM 1024
#define NH 16
#define HD 64
#define BATCH 2
#define SEQ 2048
#define M_TOTAL (BATCH * SEQ)   // 4096
#define NQKV (3 * DIM)          // 3072

// Scratch (allocation-free rule: __device__ globals)
__device__ float g_q[BATCH * NH * SEQ * HD];    // [b][h][p][d]
__device__ float g_k[BATCH * NH * SEQ * HD];
__device__ float g_v[BATCH * NH * SEQ * HD];
__device__ float g_ao[M_TOTAL * DIM];           // [b][p][h*64+d]

// ---------------------------------------------------------------------------
// Kernel 1: QKV GEMM.  C[m, c] = sum_k X[m,k] * Wqkv[k,c]
// 64x64 output tile per block, 256 threads, 4x4 microtile, K-tile 16.
// Column tile (64 wide) maps to exactly one (which, head) pair -> write
// directly into g_q / g_k / g_v in [b][h][p][d] layout.
// ---------------------------------------------------------------------------
__global__ __launch_bounds__(256) void qkv_gemm(const float* __restrict__ X,
                                                const float* __restrict__ W) {
    __shared__ float As[16][65];   // [k][m], padded
    __shared__ float Bs[16][64];   // [k][c]

    const int tid = threadIdx.x;
    const int tx = tid & 15;       // 0..15
    const int ty = tid >> 4;       // 0..15
    const int m0 = blockIdx.y * 64;
    const int c0 = blockIdx.x * 64;

    // A load: thread loads 4 consecutive k for one m row
    const int am = tid >> 2;            // 0..63
    const int ak = (tid & 3) * 4;       // 0,4,8,12
    // B load: thread loads 4 consecutive c for one k row
    const int bk = tid >> 4;            // 0..15
    const int bc = (tid & 15) * 4;

    float acc[4][4];
#pragma unroll
    for (int i = 0; i < 4; i++)
#pragma unroll
        for (int j = 0; j < 4; j++) acc[i][j] = 0.f;

    for (int k0 = 0; k0 < DIM; k0 += 16) {
        float4 av = *(const float4*)&X[(m0 + am) * DIM + k0 + ak];
        float4 bv = *(const float4*)&W[(k0 + bk) * NQKV + c0 + bc];
        __syncthreads();
        As[ak + 0][am] = av.x;
        As[ak + 1][am] = av.y;
        As[ak + 2][am] = av.z;
        As[ak + 3][am] = av.w;
        *(float4*)&Bs[bk][bc] = bv;
        __syncthreads();
#pragma unroll
        for (int k = 0; k < 16; k++) {
            float a[4], b[4];
#pragma unroll
            for (int i = 0; i < 4; i++) a[i] = As[k][ty * 4 + i];
#pragma unroll
            for (int j = 0; j < 4; j++) b[j] = Bs[k][tx * 4 + j];
#pragma unroll
            for (int i = 0; i < 4; i++)
#pragma unroll
                for (int j = 0; j < 4; j++) acc[i][j] += a[i] * b[j];
        }
    }

    // Column tile -> (which, head) is constant per block
    const int which = c0 >> 10;            // 0,1,2
    const int h = (c0 >> 6) & 15;          // head
    float* dst = (which == 0) ? g_q : ((which == 1) ? g_k : g_v);

#pragma unroll
    for (int i = 0; i < 4; i++) {
        int m = m0 + ty * 4 + i;
        int bb = m >> 11;                   // batch
        int pp = m & 2047;                  // position
        float4 v = make_float4(acc[i][0], acc[i][1], acc[i][2], acc[i][3]);
        *(float4*)&dst[(((bb * NH) + h) * SEQ + pp) * HD + tx * 4] = v;
    }
}

// ---------------------------------------------------------------------------
// Kernel 2: flash attention. grid (SEQ/64, BATCH*NH), 64 threads.
// Each thread owns one query row: q[64], o[64] in registers. K/V tiles in
// smem, read via warp-broadcast LDS.128. Online softmax in chunks of 16 keys.
// ---------------------------------------------------------------------------
__global__ __launch_bounds__(64) void attn_kernel() {
    __shared__ float Ks[64][64];   // 16 KB
    __shared__ float Vs[64][64];   // 16 KB

    const int bh = blockIdx.y;             // b*NH + h
    const int q0 = blockIdx.x * 64;
    const int tid = threadIdx.x;           // 0..63

    const float* qb = g_q + (size_t)bh * SEQ * HD;
    const float* kb = g_k + (size_t)bh * SEQ * HD;
    const float* vb = g_v + (size_t)bh * SEQ * HD;

    float q[64];
#pragma unroll
    for (int k = 0; k < 64; k += 4) {
        float4 t = *(const float4*)&qb[(q0 + tid) * HD + k];
        q[k] = t.x; q[k + 1] = t.y; q[k + 2] = t.z; q[k + 3] = t.w;
    }

    float o[64];
#pragma unroll
    for (int d = 0; d < 64; d++) o[d] = 0.f;
    float m = -1e30f;
    float l = 0.f;
    const float sc = 0.125f;   // 1/sqrt(64)

    for (int kt = 0; kt < SEQ; kt += 64) {
        __syncthreads();
        // load K/V tile: 1024 float4 each, 64 threads -> 16 float4/thread
#pragma unroll
        for (int i = 0; i < 16; i++) {
            int f = i * 64 + tid;          // float4 index
            int row = f >> 4;
            int col = (f & 15) * 4;
            *(float4*)&Ks[row][col] = *(const float4*)&kb[(kt + row) * HD + col];
            *(float4*)&Vs[row][col] = *(const float4*)&vb[(kt + row) * HD + col];
        }
        __syncthreads();

#pragma unroll 1
        for (int jc = 0; jc < 64; jc += 16) {
            float s[16];
            float mloc = -1e30f;
#pragma unroll
            for (int jj = 0; jj < 16; jj++) {
                float acc = 0.f;
#pragma unroll
                for (int k = 0; k < 64; k++) acc += q[k] * Ks[jc + jj][k];
                acc *= sc;
                s[jj] = acc;
                mloc = fmaxf(mloc, acc);
            }
            float mnew = fmaxf(m, mloc);
            float corr = __expf(m - mnew);
            m = mnew;
            l *= corr;
#pragma unroll
            for (int d = 0; d < 64; d++) o[d] *= corr;
#pragma unroll
            for (int jj = 0; jj < 16; jj++) {
                float p = __expf(s[jj] - m);
                l += p;
#pragma unroll
                for (int d = 0; d < 64; d++) o[d] += p * Vs[jc + jj][d];
            }
        }
    }

    float inv = 1.f / l;
    const int bb = bh >> 4;
    const int h = bh & 15;
    float* dst = g_ao + ((size_t)(bb * SEQ + q0 + tid) * DIM) + h * HD;
#pragma unroll
    for (int d = 0; d < 64; d += 4) {
        float4 t = make_float4(o[d] * inv, o[d + 1] * inv, o[d + 2] * inv, o[d + 3] * inv);
        *(float4*)&dst[d] = t;
    }
}

// ---------------------------------------------------------------------------
// Kernel 3: output projection + bias. out[m, n] = sum_k AO[m,k]*Wp[k,n] + b[n]
// ---------------------------------------------------------------------------
__global__ __launch_bounds__(256) void proj_gemm(const float* __restrict__ Wp,
                                                 const float* __restrict__ bias,
                                                 float* __restrict__ out) {
    __shared__ float As[16][65];
    __shared__ float Bs[16][64];

    const int tid = threadIdx.x;
    const int tx = tid & 15;
    const int ty = tid >> 4;
    const int m0 = blockIdx.y * 64;
    const int c0 = blockIdx.x * 64;

    const int am = tid >> 2;
    const int ak = (tid & 3) * 4;
    const int bk = tid >> 4;
    const int bc = (tid & 15) * 4;

    float acc[4][4];
#pragma unroll
    for (int i = 0; i < 4; i++)
#pragma unroll
        for (int j = 0; j < 4; j++) acc[i][j] = 0.f;

    for (int k0 = 0; k0 < DIM; k0 += 16) {
        float4 av = *(const float4*)&g_ao[(m0 + am) * DIM + k0 + ak];
        float4 bv = *(const float4*)&Wp[(k0 + bk) * DIM + c0 + bc];
        __syncthreads();
        As[ak + 0][am] = av.x;
        As[ak + 1][am] = av.y;
        As[ak + 2][am] = av.z;
        As[ak + 3][am] = av.w;
        *(float4*)&Bs[bk][bc] = bv;
        __syncthreads();
#pragma unroll
        for (int k = 0; k < 16; k++) {
            float a[4], b[4];
#pragma unroll
            for (int i = 0; i < 4; i++) a[i] = As[k][ty * 4 + i];
#pragma unroll
            for (int j = 0; j < 4; j++) b[j] = Bs[k][tx * 4 + j];
#pragma unroll
            for (int i = 0; i < 4; i++)
#pragma unroll
                for (int j = 0; j < 4; j++) acc[i][j] += a[i] * b[j];
        }
    }

#pragma unroll
    for (int i = 0; i < 4; i++) {
        int m = m0 + ty * 4 + i;
        int c = c0 + tx * 4;
        float4 bz = *(const float4*)&bias[c];
        float4 v = make_float4(acc[i][0] + bz.x, acc[i][1] + bz.y,
                               acc[i][2] + bz.z, acc[i][3] + bz.w);
        *(float4*)&out[m * DIM + c] = v;
    }
}

extern "C" void kernel_launch(void* const* d_in, const int* in_sizes, int n_in,
                              void* d_out, int out_size) {
    const float* x     = (const float*)d_in[0];
    const float* Wqkv  = (const float*)d_in[1];
    const float* Wproj = (const float*)d_in[2];
    const float* bproj = (const float*)d_in[3];
    float* out = (float*)d_out;

    qkv_gemm<<<dim3(NQKV / 64, M_TOTAL / 64), 256>>>(x, Wqkv);
    attn_kernel<<<dim3(SEQ / 64, BATCH * NH), 64>>>();
    proj_gemm<<<dim3(DIM / 64, M_TOTAL / 64), 256>>>(Wproj, bproj, out);
}

// round 4
// speedup vs baseline: 1.3368x; 1.3368x over previous
#include <cuda_runtime.h>
#include <cuda_bf16.h>
#include <cstdint>

#define DIM 1024
#define NH 16
#define HD 64
#define BATCH 2
#define SEQ 2048
#define MT 4096                 // total rows
#define NQKV 3072

// ---------------------------------------------------------------------------
// Scratch (__device__ globals; no allocation allowed)
// ---------------------------------------------------------------------------
__device__ float g_q[BATCH * NH * SEQ * HD];
__device__ float g_k[BATCH * NH * SEQ * HD];
__device__ float g_v[BATCH * NH * SEQ * HD];
__device__ float g_ao[MT * DIM];

__device__ uint16_t g_xhi[MT * DIM],   g_xlo[MT * DIM];       // X split bf16
__device__ uint16_t g_wqt_hi[NQKV * DIM], g_wqt_lo[NQKV * DIM]; // Wqkv^T [N][K]
__device__ uint16_t g_wpt_hi[DIM * DIM],  g_wpt_lo[DIM * DIM];  // Wproj^T [N][K]
__device__ uint16_t g_aohi[MT * DIM],  g_aolo[MT * DIM];      // attn out split

// ---------------------------------------------------------------------------
// helpers
// ---------------------------------------------------------------------------
__device__ __forceinline__ uint32_t smem_u32(const void* p) {
    uint32_t a;
    asm("{ .reg .u64 t; cvta.to.shared.u64 t, %1; cvt.u32.u64 %0, t; }" : "=r"(a) : "l"(p));
    return a;
}

__device__ __forceinline__ uint16_t hi16(float x) {
    return (uint16_t)(__float_as_uint(x) >> 16);
}
__device__ __forceinline__ uint16_t lo16(float x) {
    float h = __uint_as_float(__float_as_uint(x) & 0xffff0000u);
    __nv_bfloat16 b = __float2bfloat16_rn(x - h);
    return *reinterpret_cast<uint16_t*>(&b);
}

#define CP_ASYNC16(dst, src) \
    asm volatile("cp.async.cg.shared.global [%0], [%1], 16;" :: "r"(dst), "l"(src))
#define CP_COMMIT() asm volatile("cp.async.commit_group;")
#define CP_WAIT1()  asm volatile("cp.async.wait_group 1;")
#define CP_WAIT0()  asm volatile("cp.async.wait_group 0;")

#define LDM4(r, a)                                                                  \
    asm volatile("ldmatrix.sync.aligned.m8n8.x4.shared.b16 {%0,%1,%2,%3}, [%4];"   \
        : "=r"((r)[0]), "=r"((r)[1]), "=r"((r)[2]), "=r"((r)[3]) : "r"(a))

#define MMA16816(c, a, b)                                                           \
    asm volatile("mma.sync.aligned.m16n8k16.row.col.f32.bf16.bf16.f32 "            \
        "{%0,%1,%2,%3}, {%4,%5,%6,%7}, {%8,%9}, {%0,%1,%2,%3};"                    \
        : "+f"((c)[0]), "+f"((c)[1]), "+f"((c)[2]), "+f"((c)[3])                   \
        : "r"((a)[0]), "r"((a)[1]), "r"((a)[2]), "r"((a)[3]),                      \
          "r"((b)[0]), "r"((b)[1]))

// ---------------------------------------------------------------------------
// conversion kernels
// ---------------------------------------------------------------------------
__global__ void cvt_split(const float* __restrict__ src_in, int sel, int n) {
    const float* src = (sel == 1) ? g_ao : src_in;
    uint16_t* hi = (sel == 1) ? g_aohi : g_xhi;
    uint16_t* lo = (sel == 1) ? g_aolo : g_xlo;
    int n4 = n >> 2;
    for (int i = blockIdx.x * blockDim.x + threadIdx.x; i < n4;
         i += gridDim.x * blockDim.x) {
        float4 v = ((const float4*)src)[i];
        uint2 h, l;
        h.x = (uint32_t)hi16(v.x) | ((uint32_t)hi16(v.y) << 16);
        h.y = (uint32_t)hi16(v.z) | ((uint32_t)hi16(v.w) << 16);
        l.x = (uint32_t)lo16(v.x) | ((uint32_t)lo16(v.y) << 16);
        l.y = (uint32_t)lo16(v.z) | ((uint32_t)lo16(v.w) << 16);
        ((uint2*)hi)[i] = h;
        ((uint2*)lo)[i] = l;
    }
}

// W [K=DIM][N] row-major -> Wt hi/lo [N][DIM]
__global__ void cvt_splitT(const float* __restrict__ src, int sel, int N) {
    __shared__ float s[32][33];
    uint16_t* hi = sel ? g_wpt_hi : g_wqt_hi;
    uint16_t* lo = sel ? g_wpt_lo : g_wqt_lo;
    const int bn = blockIdx.x * 32, bk = blockIdx.y * 32;
    const int tx = threadIdx.x, ty = threadIdx.y;    // 32 x 8
#pragma unroll
    for (int i = 0; i < 4; i++)
        s[ty + i * 8][tx] = src[(size_t)(bk + ty + i * 8) * N + bn + tx];
    __syncthreads();
#pragma unroll
    for (int i = 0; i < 4; i++) {
        float v = s[tx][ty + i * 8];
        size_t o = (size_t)(bn + ty + i * 8) * DIM + bk + tx;
        hi[o] = hi16(v);
        lo[o] = lo16(v);
    }
}

// ---------------------------------------------------------------------------
// mma.sync split-bf16 GEMM: C[m,n] = sum_k A[m,k]*B[k,n]
// A hi/lo [MT][DIM], Bt hi/lo [N][DIM]. CTA 128x128, BK=32, 8 warps (64x32).
// mode 0: route to g_q/g_k/g_v ([b][h][p][d]); mode 1: Cout + bias.
// ---------------------------------------------------------------------------
#define STR 80                       // smem bytes per row (64B data + 16B pad)
#define TILE_B (128 * STR)           // 10240
#define BUF_B (4 * TILE_B)           // 40960
#define GSMEM (2 * BUF_B)            // 81920

__global__ __launch_bounds__(256, 1) void gemm_mma(int mode,
                                                   const float* __restrict__ bias,
                                                   float* __restrict__ Cout) {
    extern __shared__ char sm[];
    const uint32_t sb = smem_u32(sm);
    const int tid = threadIdx.x;
    const int wid = tid >> 5;
    const int lane = tid & 31;
    const int m0 = blockIdx.y * 128;
    const int n0 = blockIdx.x * 128;

    const uint16_t* Ahi = mode ? g_aohi : g_xhi;
    const uint16_t* Alo = mode ? g_aolo : g_xlo;
    const uint16_t* Bhi = mode ? g_wpt_hi : g_wqt_hi;
    const uint16_t* Blo = mode ? g_wpt_lo : g_wqt_lo;

    // cp.async load of one BK=32 chunk into buffer `buf`
    auto load_buf = [&](int c, int buf) {
        const uint32_t bo = sb + buf * BUF_B;
        const int k0 = c * 32;
#pragma unroll
        for (int i = 0; i < 2; i++) {
            int idx = i * 256 + tid;
            int row = idx >> 2;
            int ch = idx & 3;
            uint32_t so = row * STR + ch * 16;
            size_t ga = (size_t)(m0 + row) * DIM + k0 + ch * 8;
            size_t gb = (size_t)(n0 + row) * DIM + k0 + ch * 8;
            CP_ASYNC16(bo + 0 * TILE_B + so, Ahi + ga);
            CP_ASYNC16(bo + 1 * TILE_B + so, Alo + ga);
            CP_ASYNC16(bo + 2 * TILE_B + so, Bhi + gb);
            CP_ASYNC16(bo + 3 * TILE_B + so, Blo + gb);
        }
        CP_COMMIT();
    };

    load_buf(0, 0);
    load_buf(1, 1);

    const int mBase = (wid >> 2) * 64;
    const int nBase = (wid & 3) * 32;
    const int aRow = lane & 15;
    const int aCB = (lane >> 4) * 16;
    const int bRowOff = (lane & 7) + ((lane >> 4) & 1) * 8;
    const int bCB = ((lane >> 3) & 1) * 16;

    float acc[4][4][4];
#pragma unroll
    for (int i = 0; i < 4; i++)
#pragma unroll
        for (int j = 0; j < 4; j++)
#pragma unroll
            for (int r = 0; r < 4; r++) acc[i][j][r] = 0.f;

    for (int c = 0; c < 32; c++) {
        const int buf = c & 1;
        if (c < 31) { CP_WAIT1(); } else { CP_WAIT0(); }
        __syncthreads();
        const uint32_t bo = sb + buf * BUF_B;
#pragma unroll
        for (int k16 = 0; k16 < 2; k16++) {
            uint32_t ahi[4][4], alo[4][4], bhi[8], blo[8];
#pragma unroll
            for (int i = 0; i < 4; i++) {
                uint32_t ra = bo + (mBase + i * 16 + aRow) * STR + aCB + k16 * 32;
                LDM4(ahi[i], ra);
                LDM4(alo[i], ra + TILE_B);
            }
#pragma unroll
            for (int j = 0; j < 2; j++) {
                uint32_t rb = bo + 2 * TILE_B +
                              (nBase + j * 16 + bRowOff) * STR + bCB + k16 * 32;
                LDM4(&bhi[j * 4], rb);
                LDM4(&blo[j * 4], rb + TILE_B);
            }
#pragma unroll
            for (int i = 0; i < 4; i++)
#pragma unroll
                for (int j = 0; j < 4; j++) {
                    uint32_t* bh = &bhi[(j >> 1) * 4 + (j & 1) * 2];
                    uint32_t* bl = &blo[(j >> 1) * 4 + (j & 1) * 2];
                    MMA16816(acc[i][j], ahi[i], bh);
                    MMA16816(acc[i][j], ahi[i], bl);
                    MMA16816(acc[i][j], alo[i], bh);
                }
        }
        __syncthreads();
        if (c + 2 < 32) load_buf(c + 2, buf);
    }

    // epilogue
    const int g = lane >> 2, tg = lane & 3;
#pragma unroll
    for (int i = 0; i < 4; i++) {
#pragma unroll
        for (int j = 0; j < 4; j++) {
            int row = m0 + mBase + i * 16 + g;
            int col = n0 + nBase + j * 8 + tg * 2;
            if (mode == 0) {
                int which = col >> 10;
                int h = (col >> 6) & 15;
                int d = col & 63;
                float* dst = ((which == 0) ? g_q : (which == 1) ? g_k : g_v) +
                             ((size_t)((row >> 11) * NH + h) * SEQ + (row & 2047)) * HD + d;
                *(float2*)dst = make_float2(acc[i][j][0], acc[i][j][1]);
                *(float2*)(dst + 8 * HD) = make_float2(acc[i][j][2], acc[i][j][3]);
            } else {
                float2 bz = *(const float2*)&bias[col];
                *(float2*)&Cout[(size_t)row * DIM + col] =
                    make_float2(acc[i][j][0] + bz.x, acc[i][j][1] + bz.y);
                *(float2*)&Cout[(size_t)(row + 8) * DIM + col] =
                    make_float2(acc[i][j][2] + bz.x, acc[i][j][3] + bz.y);
            }
        }
    }
}

// ---------------------------------------------------------------------------
// Flash attention (fp32, unchanged — passed R2 at rel_err 6e-7)
// ---------------------------------------------------------------------------
__global__ __launch_bounds__(64) void attn_kernel() {
    __shared__ float Ks[64][64];
    __shared__ float Vs[64][64];

    const int bh = blockIdx.y;
    const int q0 = blockIdx.x * 64;
    const int tid = threadIdx.x;

    const float* qb = g_q + (size_t)bh * SEQ * HD;
    const float* kb = g_k + (size_t)bh * SEQ * HD;
    const float* vb = g_v + (size_t)bh * SEQ * HD;

    float q[64];
#pragma unroll
    for (int k = 0; k < 64; k += 4) {
        float4 t = *(const float4*)&qb[(q0 + tid) * HD + k];
        q[k] = t.x; q[k + 1] = t.y; q[k + 2] = t.z; q[k + 3] = t.w;
    }

    float o[64];
#pragma unroll
    for (int d = 0; d < 64; d++) o[d] = 0.f;
    float m = -1e30f;
    float l = 0.f;
    const float sc = 0.125f;

    for (int kt = 0; kt < SEQ; kt += 64) {
        __syncthreads();
#pragma unroll
        for (int i = 0; i < 16; i++) {
            int f = i * 64 + tid;
            int row = f >> 4;
            int col = (f & 15) * 4;
            *(float4*)&Ks[row][col] = *(const float4*)&kb[(kt + row) * HD + col];
            *(float4*)&Vs[row][col] = *(const float4*)&vb[(kt + row) * HD + col];
        }
        __syncthreads();

#pragma unroll 1
        for (int jc = 0; jc < 64; jc += 16) {
            float s[16];
            float mloc = -1e30f;
#pragma unroll
            for (int jj = 0; jj < 16; jj++) {
                float acc = 0.f;
#pragma unroll
                for (int k = 0; k < 64; k++) acc += q[k] * Ks[jc + jj][k];
                acc *= sc;
                s[jj] = acc;
                mloc = fmaxf(mloc, acc);
            }
            float mnew = fmaxf(m, mloc);
            float corr = __expf(m - mnew);
            m = mnew;
            l *= corr;
#pragma unroll
            for (int d = 0; d < 64; d++) o[d] *= corr;
#pragma unroll
            for (int jj = 0; jj < 16; jj++) {
                float p = __expf(s[jj] - m);
                l += p;
#pragma unroll
                for (int d = 0; d < 64; d++) o[d] += p * Vs[jc + jj][d];
            }
        }
    }

    float inv = 1.f / l;
    const int bb = bh >> 4;
    const int h = bh & 15;
    float* dst = g_ao + ((size_t)(bb * SEQ + q0 + tid) * DIM) + h * HD;
#pragma unroll
    for (int d = 0; d < 64; d += 4) {
        float4 t = make_float4(o[d] * inv, o[d + 1] * inv, o[d + 2] * inv, o[d + 3] * inv);
        *(float4*)&dst[d] = t;
    }
}

extern "C" void kernel_launch(void* const* d_in, const int* in_sizes, int n_in,
                              void* d_out, int out_size) {
    const float* x     = (const float*)d_in[0];
    const float* Wqkv  = (const float*)d_in[1];
    const float* Wproj = (const float*)d_in[2];
    const float* bproj = (const float*)d_in[3];
    float* out = (float*)d_out;

    static int smem_set = 0;
    if (!smem_set) {
        cudaFuncSetAttribute(gemm_mma, cudaFuncAttributeMaxDynamicSharedMemorySize, GSMEM);
        smem_set = 1;
    }

    cvt_split<<<1024, 256>>>(x, 0, MT * DIM);
    cvt_splitT<<<dim3(NQKV / 32, DIM / 32), dim3(32, 8)>>>(Wqkv, 0, NQKV);
    cvt_splitT<<<dim3(DIM / 32, DIM / 32), dim3(32, 8)>>>(Wproj, 1, DIM);

    gemm_mma<<<dim3(NQKV / 128, MT / 128), 256, GSMEM>>>(0, nullptr, nullptr);
    attn_kernel<<<dim3(SEQ / 64, BATCH * NH), 64>>>();
    cvt_split<<<1024, 256>>>(nullptr, 1, MT * DIM);
    gemm_mma<<<dim3(DIM / 128, MT / 128), 256, GSMEM>>>(1, bproj, out);
}

// round 5
// speedup vs baseline: 3.6334x; 2.7179x over previous
#include <cuda_runtime.h>
#include <cuda_bf16.h>
#include <cstdint>

#define DIM 1024
#define NH 16
#define HD 64
#define BATCH 2
#define SEQ 2048
#define MT 4096
#define NQKV 3072
#define SC 0.125f

// ---------------------------------------------------------------------------
// Scratch (__device__ globals)
// ---------------------------------------------------------------------------
__device__ uint16_t g_xhi[MT * DIM],   g_xlo[MT * DIM];          // X split
__device__ uint16_t g_wqt_hi[NQKV * DIM], g_wqt_lo[NQKV * DIM];  // Wqkv^T [N][K]
__device__ uint16_t g_wpt_hi[DIM * DIM],  g_wpt_lo[DIM * DIM];   // Wproj^T [N][K]
__device__ uint16_t g_qhi[BATCH * NH * SEQ * HD], g_qlo[BATCH * NH * SEQ * HD];
__device__ uint16_t g_khi[BATCH * NH * SEQ * HD], g_klo[BATCH * NH * SEQ * HD];
__device__ uint16_t g_vt [BATCH * NH * HD * SEQ];                // V^T [bh][d][p]
__device__ uint16_t g_aohi[MT * DIM], g_aolo[MT * DIM];          // attn out split

// ---------------------------------------------------------------------------
// helpers
// ---------------------------------------------------------------------------
__device__ __forceinline__ uint32_t smem_u32(const void* p) {
    uint32_t a;
    asm("{ .reg .u64 t; cvta.to.shared.u64 t, %1; cvt.u32.u64 %0, t; }" : "=r"(a) : "l"(p));
    return a;
}
__device__ __forceinline__ uint16_t hi16(float x) {
    return (uint16_t)(__float_as_uint(x) >> 16);
}
__device__ __forceinline__ uint16_t lo16(float x) {
    float h = __uint_as_float(__float_as_uint(x) & 0xffff0000u);
    __nv_bfloat16 b = __float2bfloat16_rn(x - h);
    return *reinterpret_cast<uint16_t*>(&b);
}
__device__ __forceinline__ uint16_t bf16rn(float x) {
    __nv_bfloat16 b = __float2bfloat16_rn(x);
    return *reinterpret_cast<uint16_t*>(&b);
}
__device__ __forceinline__ uint32_t packbf2(float a, float b) {
    __nv_bfloat162 t = __floats2bfloat162_rn(a, b);   // x=a (low), y=b (high)
    return *reinterpret_cast<uint32_t*>(&t);
}

#define CP_ASYNC16(dst, src) \
    asm volatile("cp.async.cg.shared.global [%0], [%1], 16;" :: "r"(dst), "l"(src))
#define CP_COMMIT() asm volatile("cp.async.commit_group;")
#define CP_WAIT1()  asm volatile("cp.async.wait_group 1;")
#define CP_WAIT0()  asm volatile("cp.async.wait_group 0;")

#define LDM4(r, a)                                                                  \
    asm volatile("ldmatrix.sync.aligned.m8n8.x4.shared.b16 {%0,%1,%2,%3}, [%4];"   \
        : "=r"((r)[0]), "=r"((r)[1]), "=r"((r)[2]), "=r"((r)[3]) : "r"(a))

#define MMA16816(c, a, b)                                                           \
    asm volatile("mma.sync.aligned.m16n8k16.row.col.f32.bf16.bf16.f32 "            \
        "{%0,%1,%2,%3}, {%4,%5,%6,%7}, {%8,%9}, {%0,%1,%2,%3};"                    \
        : "+f"((c)[0]), "+f"((c)[1]), "+f"((c)[2]), "+f"((c)[3])                   \
        : "r"((a)[0]), "r"((a)[1]), "r"((a)[2]), "r"((a)[3]),                      \
          "r"((b)[0]), "r"((b)[1]))

// ---------------------------------------------------------------------------
// conversion kernels
// ---------------------------------------------------------------------------
__global__ void cvt_split(const float* __restrict__ src, int n) {
    int n4 = n >> 2;
    for (int i = blockIdx.x * blockDim.x + threadIdx.x; i < n4;
         i += gridDim.x * blockDim.x) {
        float4 v = ((const float4*)src)[i];
        uint2 h, l;
        h.x = (uint32_t)hi16(v.x) | ((uint32_t)hi16(v.y) << 16);
        h.y = (uint32_t)hi16(v.z) | ((uint32_t)hi16(v.w) << 16);
        l.x = (uint32_t)lo16(v.x) | ((uint32_t)lo16(v.y) << 16);
        l.y = (uint32_t)lo16(v.z) | ((uint32_t)lo16(v.w) << 16);
        ((uint2*)g_xhi)[i] = h;
        ((uint2*)g_xlo)[i] = l;
    }
}

__global__ void cvt_splitT(const float* __restrict__ src, int sel, int N) {
    __shared__ float s[32][33];
    uint16_t* hi = sel ? g_wpt_hi : g_wqt_hi;
    uint16_t* lo = sel ? g_wpt_lo : g_wqt_lo;
    const int bn = blockIdx.x * 32, bk = blockIdx.y * 32;
    const int tx = threadIdx.x, ty = threadIdx.y;
#pragma unroll
    for (int i = 0; i < 4; i++)
        s[ty + i * 8][tx] = src[(size_t)(bk + ty + i * 8) * N + bn + tx];
    __syncthreads();
#pragma unroll
    for (int i = 0; i < 4; i++) {
        float v = s[tx][ty + i * 8];
        size_t o = (size_t)(bn + ty + i * 8) * DIM + bk + tx;
        hi[o] = hi16(v);
        lo[o] = lo16(v);
    }
}

// ---------------------------------------------------------------------------
// mma.sync split-bf16 GEMM (CTA 128x128, BK=32, 8 warps of 64x32)
// mode 0: epilogue -> g_qhi/lo, g_khi/lo ([bh][p][d]), g_vt ([bh][d][p])
// mode 1: epilogue -> Cout + bias
// ---------------------------------------------------------------------------
#define STR 80
#define TILE_B (128 * STR)
#define BUF_B (4 * TILE_B)
#define GSMEM (2 * BUF_B)

__global__ __launch_bounds__(256, 1) void gemm_mma(int mode,
                                                   const float* __restrict__ bias,
                                                   float* __restrict__ Cout) {
    extern __shared__ char sm[];
    const uint32_t sb = smem_u32(sm);
    const int tid = threadIdx.x;
    const int wid = tid >> 5;
    const int lane = tid & 31;
    const int m0 = blockIdx.y * 128;
    const int n0 = blockIdx.x * 128;

    const uint16_t* Ahi = mode ? g_aohi : g_xhi;
    const uint16_t* Alo = mode ? g_aolo : g_xlo;
    const uint16_t* Bhi = mode ? g_wpt_hi : g_wqt_hi;
    const uint16_t* Blo = mode ? g_wpt_lo : g_wqt_lo;

    auto load_buf = [&](int c, int buf) {
        const uint32_t bo = sb + buf * BUF_B;
        const int k0 = c * 32;
#pragma unroll
        for (int i = 0; i < 2; i++) {
            int idx = i * 256 + tid;
            int row = idx >> 2;
            int ch = idx & 3;
            uint32_t so = row * STR + ch * 16;
            size_t ga = (size_t)(m0 + row) * DIM + k0 + ch * 8;
            size_t gb = (size_t)(n0 + row) * DIM + k0 + ch * 8;
            CP_ASYNC16(bo + 0 * TILE_B + so, Ahi + ga);
            CP_ASYNC16(bo + 1 * TILE_B + so, Alo + ga);
            CP_ASYNC16(bo + 2 * TILE_B + so, Bhi + gb);
            CP_ASYNC16(bo + 3 * TILE_B + so, Blo + gb);
        }
        CP_COMMIT();
    };

    load_buf(0, 0);
    load_buf(1, 1);

    const int mBase = (wid >> 2) * 64;
    const int nBase = (wid & 3) * 32;
    const int aRow = lane & 15;
    const int aCB = (lane >> 4) * 16;
    const int bRowOff = (lane & 7) + ((lane >> 4) & 1) * 8;
    const int bCB = ((lane >> 3) & 1) * 16;

    float acc[4][4][4];
#pragma unroll
    for (int i = 0; i < 4; i++)
#pragma unroll
        for (int j = 0; j < 4; j++)
#pragma unroll
            for (int r = 0; r < 4; r++) acc[i][j][r] = 0.f;

    for (int c = 0; c < 32; c++) {
        const int buf = c & 1;
        if (c < 31) { CP_WAIT1(); } else { CP_WAIT0(); }
        __syncthreads();
        const uint32_t bo = sb + buf * BUF_B;
#pragma unroll
        for (int k16 = 0; k16 < 2; k16++) {
            uint32_t ahi[4][4], alo[4][4], bhi[8], blo[8];
#pragma unroll
            for (int i = 0; i < 4; i++) {
                uint32_t ra = bo + (mBase + i * 16 + aRow) * STR + aCB + k16 * 32;
                LDM4(ahi[i], ra);
                LDM4(alo[i], ra + TILE_B);
            }
#pragma unroll
            for (int j = 0; j < 2; j++) {
                uint32_t rb = bo + 2 * TILE_B +
                              (nBase + j * 16 + bRowOff) * STR + bCB + k16 * 32;
                LDM4(&bhi[j * 4], rb);
                LDM4(&blo[j * 4], rb + TILE_B);
            }
#pragma unroll
            for (int i = 0; i < 4; i++)
#pragma unroll
                for (int j = 0; j < 4; j++) {
                    uint32_t* bh = &bhi[(j >> 1) * 4 + (j & 1) * 2];
                    uint32_t* bl = &blo[(j >> 1) * 4 + (j & 1) * 2];
                    MMA16816(acc[i][j], ahi[i], bh);
                    MMA16816(acc[i][j], ahi[i], bl);
                    MMA16816(acc[i][j], alo[i], bh);
                }
        }
        __syncthreads();
        if (c + 2 < 32) load_buf(c + 2, buf);
    }

    const int g = lane >> 2, tg = lane & 3;
#pragma unroll
    for (int i = 0; i < 4; i++) {
#pragma unroll
        for (int j = 0; j < 4; j++) {
            int row = m0 + mBase + i * 16 + g;
            int col = n0 + nBase + j * 8 + tg * 2;
            float v0 = acc[i][j][0], v1 = acc[i][j][1];
            float v2 = acc[i][j][2], v3 = acc[i][j][3];
            if (mode == 0) {
                int which = col >> 10;
                int h = (col >> 6) & 15;
                int d = col & 63;
                int b = row >> 11, p = row & 2047;
                if (which < 2) {
                    uint16_t* hb = which ? g_khi : g_qhi;
                    uint16_t* lb = which ? g_klo : g_qlo;
                    size_t off = ((size_t)(b * NH + h) * SEQ + p) * HD + d;
                    *(uint32_t*)(hb + off) = (uint32_t)hi16(v0) | ((uint32_t)hi16(v1) << 16);
                    *(uint32_t*)(lb + off) = (uint32_t)lo16(v0) | ((uint32_t)lo16(v1) << 16);
                    *(uint32_t*)(hb + off + 8 * HD) = (uint32_t)hi16(v2) | ((uint32_t)hi16(v3) << 16);
                    *(uint32_t*)(lb + off + 8 * HD) = (uint32_t)lo16(v2) | ((uint32_t)lo16(v3) << 16);
                } else {
                    size_t vb = ((size_t)(b * NH + h) * HD + d) * SEQ + p;
                    g_vt[vb] = bf16rn(v0);
                    g_vt[vb + SEQ] = bf16rn(v1);
                    g_vt[vb + 8] = bf16rn(v2);
                    g_vt[vb + SEQ + 8] = bf16rn(v3);
                }
            } else {
                float2 bz = *(const float2*)&bias[col];
                *(float2*)&Cout[(size_t)row * DIM + col] =
                    make_float2(v0 + bz.x, v1 + bz.y);
                *(float2*)&Cout[(size_t)(row + 8) * DIM + col] =
                    make_float2(v2 + bz.x, v3 + bz.y);
            }
        }
    }
}

// ---------------------------------------------------------------------------
// Flash attention, mma.sync. Grid (SEQ/128, BH=32), 256 threads (8 warps x 16 q-rows).
// S = Q K^T in split-bf16 (3 MMA); PV in plain bf16, V pre-transposed.
// Writes g_aohi/g_aolo split directly.
// ---------------------------------------------------------------------------
#define STRK 144
#define STRV 272
#define KTILE_B (128 * STRK)          // 18432
#define VTILE_B (64 * STRV)           // 17408
#define ABUF (2 * KTILE_B + VTILE_B)  // 54272
#define ASMEM (2 * ABUF)              // 108544

__global__ __launch_bounds__(256, 1) void attn_mma() {
    extern __shared__ char sm[];
    const uint32_t sb = smem_u32(sm);
    const int tid = threadIdx.x;
    const int wid = tid >> 5;
    const int lane = tid & 31;
    const int bh = blockIdx.y;
    const int q0 = blockIdx.x * 128;

    const uint16_t* Qh = g_qhi + ((size_t)bh * SEQ + q0) * HD;
    const uint16_t* Ql = g_qlo + ((size_t)bh * SEQ + q0) * HD;
    const uint16_t* Kh = g_khi + (size_t)bh * SEQ * HD;
    const uint16_t* Kl = g_klo + (size_t)bh * SEQ * HD;
    const uint16_t* Vt = g_vt + (size_t)bh * HD * SEQ;

    // stage Q (hi->buf0 K region, lo->buf0 Klo region)
#pragma unroll
    for (int i = 0; i < 4; i++) {
        int idx = tid + i * 256;
        int row = idx >> 3, ch = idx & 7;
        CP_ASYNC16(sb + row * STRK + ch * 16, Qh + row * HD + ch * 8);
        CP_ASYNC16(sb + KTILE_B + row * STRK + ch * 16, Ql + row * HD + ch * 8);
    }
    CP_COMMIT();
    CP_WAIT0();
    __syncthreads();

    const int aRow = lane & 15, aCB = (lane >> 4) * 16;
    uint32_t qh[4][4], ql[4][4];
#pragma unroll
    for (int ks = 0; ks < 4; ks++) {
        uint32_t ra = sb + (wid * 16 + aRow) * STRK + aCB + ks * 32;
        LDM4(qh[ks], ra);
        LDM4(ql[ks], ra + KTILE_B);
    }
    __syncthreads();

    auto loadc = [&](int c) {
        const uint32_t bo = sb + (c & 1) * ABUF;
        const int k0 = c * 128;
#pragma unroll
        for (int i = 0; i < 4; i++) {
            int idx = tid + i * 256;
            int row = idx >> 3, ch = idx & 7;
            CP_ASYNC16(bo + row * STRK + ch * 16, Kh + (size_t)(k0 + row) * HD + ch * 8);
            CP_ASYNC16(bo + KTILE_B + row * STRK + ch * 16, Kl + (size_t)(k0 + row) * HD + ch * 8);
        }
#pragma unroll
        for (int i = 0; i < 4; i++) {
            int idx = tid + i * 256;
            int row = idx >> 4, ch = idx & 15;
            CP_ASYNC16(bo + 2 * KTILE_B + row * STRV + ch * 16,
                       Vt + (size_t)row * SEQ + k0 + ch * 8);
        }
        CP_COMMIT();
    };

    loadc(0);
    loadc(1);

    const int bRowOff = (lane & 7) + ((lane >> 4) & 1) * 8;
    const int bCB = ((lane >> 3) & 1) * 16;
    const int g = lane >> 2, tg = lane & 3;

    float o[8][4];
#pragma unroll
    for (int j = 0; j < 8; j++)
#pragma unroll
        for (int r = 0; r < 4; r++) o[j][r] = 0.f;
    float m_g = -1e30f, m_g8 = -1e30f, l_g = 0.f, l_g8 = 0.f;

    for (int c = 0; c < 16; c++) {
        if (c < 15) { CP_WAIT1(); } else { CP_WAIT0(); }
        __syncthreads();
        const uint32_t bo = sb + (c & 1) * ABUF;

        float s[16][4];
#pragma unroll
        for (int j = 0; j < 16; j++)
#pragma unroll
            for (int r = 0; r < 4; r++) s[j][r] = 0.f;

#pragma unroll
        for (int ks = 0; ks < 4; ks++) {
#pragma unroll
            for (int n16 = 0; n16 < 8; n16++) {
                uint32_t kb[4], klb[4];
                uint32_t rb = bo + (n16 * 16 + bRowOff) * STRK + bCB + ks * 32;
                LDM4(kb, rb);
                LDM4(klb, rb + KTILE_B);
                MMA16816(s[2 * n16], qh[ks], kb);
                MMA16816(s[2 * n16], qh[ks], klb);
                MMA16816(s[2 * n16], ql[ks], kb);
                MMA16816(s[2 * n16 + 1], qh[ks], kb + 2);
                MMA16816(s[2 * n16 + 1], qh[ks], klb + 2);
                MMA16816(s[2 * n16 + 1], ql[ks], kb + 2);
            }
        }

        // row maxes (scaled)
        float vg = -1e30f, vg8 = -1e30f;
#pragma unroll
        for (int j = 0; j < 16; j++) {
            vg = fmaxf(vg, fmaxf(s[j][0], s[j][1]));
            vg8 = fmaxf(vg8, fmaxf(s[j][2], s[j][3]));
        }
        vg = fmaxf(vg, __shfl_xor_sync(0xffffffffu, vg, 1));
        vg = fmaxf(vg, __shfl_xor_sync(0xffffffffu, vg, 2));
        vg8 = fmaxf(vg8, __shfl_xor_sync(0xffffffffu, vg8, 1));
        vg8 = fmaxf(vg8, __shfl_xor_sync(0xffffffffu, vg8, 2));

        float mn_g = fmaxf(m_g, vg * SC);
        float mn_g8 = fmaxf(m_g8, vg8 * SC);
        float cr_g = __expf(m_g - mn_g);
        float cr_g8 = __expf(m_g8 - mn_g8);
        m_g = mn_g; m_g8 = mn_g8;
        l_g *= cr_g; l_g8 *= cr_g8;
#pragma unroll
        for (int j = 0; j < 8; j++) {
            o[j][0] *= cr_g; o[j][1] *= cr_g;
            o[j][2] *= cr_g8; o[j][3] *= cr_g8;
        }

        uint32_t pa[8][4];
        float sl_g = 0.f, sl_g8 = 0.f;
#pragma unroll
        for (int j = 0; j < 8; j++) {
            float p0 = __expf(s[2 * j][0] * SC - m_g);
            float p1 = __expf(s[2 * j][1] * SC - m_g);
            float p2 = __expf(s[2 * j][2] * SC - m_g8);
            float p3 = __expf(s[2 * j][3] * SC - m_g8);
            float p4 = __expf(s[2 * j + 1][0] * SC - m_g);
            float p5 = __expf(s[2 * j + 1][1] * SC - m_g);
            float p6 = __expf(s[2 * j + 1][2] * SC - m_g8);
            float p7 = __expf(s[2 * j + 1][3] * SC - m_g8);
            sl_g += p0 + p1 + p4 + p5;
            sl_g8 += p2 + p3 + p6 + p7;
            pa[j][0] = packbf2(p0, p1);
            pa[j][1] = packbf2(p2, p3);
            pa[j][2] = packbf2(p4, p5);
            pa[j][3] = packbf2(p6, p7);
        }
        sl_g += __shfl_xor_sync(0xffffffffu, sl_g, 1);
        sl_g += __shfl_xor_sync(0xffffffffu, sl_g, 2);
        sl_g8 += __shfl_xor_sync(0xffffffffu, sl_g8, 1);
        sl_g8 += __shfl_xor_sync(0xffffffffu, sl_g8, 2);
        l_g += sl_g; l_g8 += sl_g8;

        // PV
#pragma unroll
        for (int kt = 0; kt < 8; kt++) {
#pragma unroll
            for (int nv = 0; nv < 4; nv++) {
                uint32_t vb[4];
                uint32_t rb = bo + 2 * KTILE_B + (nv * 16 + bRowOff) * STRV + bCB + kt * 32;
                LDM4(vb, rb);
                MMA16816(o[2 * nv], pa[kt], vb);
                MMA16816(o[2 * nv + 1], pa[kt], vb + 2);
            }
        }
        __syncthreads();
        if (c + 2 < 16) loadc(c + 2);
    }

    float ig = 1.f / l_g, ig8 = 1.f / l_g8;
    const int b = bh >> 4, h = bh & 15;
    size_t base = ((size_t)(b * SEQ + q0 + wid * 16 + g)) * DIM + h * HD;
#pragma unroll
    for (int j = 0; j < 8; j++) {
        int d = (j >> 1) * 16 + (j & 1) * 8 + tg * 2;
        float x0 = o[j][0] * ig, x1 = o[j][1] * ig;
        float x2 = o[j][2] * ig8, x3 = o[j][3] * ig8;
        *(uint32_t*)(g_aohi + base + d) = (uint32_t)hi16(x0) | ((uint32_t)hi16(x1) << 16);
        *(uint32_t*)(g_aolo + base + d) = (uint32_t)lo16(x0) | ((uint32_t)lo16(x1) << 16);
        *(uint32_t*)(g_aohi + base + 8 * DIM + d) = (uint32_t)hi16(x2) | ((uint32_t)hi16(x3) << 16);
        *(uint32_t*)(g_aolo + base + 8 * DIM + d) = (uint32_t)lo16(x2) | ((uint32_t)lo16(x3) << 16);
    }
}

extern "C" void kernel_launch(void* const* d_in, const int* in_sizes, int n_in,
                              void* d_out, int out_size) {
    const float* x     = (const float*)d_in[0];
    const float* Wqkv  = (const float*)d_in[1];
    const float* Wproj = (const float*)d_in[2];
    const float* bproj = (const float*)d_in[3];
    float* out = (float*)d_out;

    static int smem_set = 0;
    if (!smem_set) {
        cudaFuncSetAttribute(gemm_mma, cudaFuncAttributeMaxDynamicSharedMemorySize, GSMEM);
        cudaFuncSetAttribute(attn_mma, cudaFuncAttributeMaxDynamicSharedMemorySize, ASMEM);
        smem_set = 1;
    }

    cvt_split<<<1024, 256>>>(x, MT * DIM);
    cvt_splitT<<<dim3(NQKV / 32, DIM / 32), dim3(32, 8)>>>(Wqkv, 0, NQKV);
    cvt_splitT<<<dim3(DIM / 32, DIM / 32), dim3(32, 8)>>>(Wproj, 1, DIM);

    gemm_mma<<<dim3(NQKV / 128, MT / 128), 256, GSMEM>>>(0, nullptr, nullptr);
    attn_mma<<<dim3(SEQ / 128, BATCH * NH), 256, ASMEM>>>();
    gemm_mma<<<dim3(DIM / 128, MT / 128), 256, GSMEM>>>(1, bproj, out);
}